// round 6
// baseline (speedup 1.0000x reference)
#include <cuda_runtime.h>
#include <cuda_bf16.h>

// Problem constants (fixed shapes from reference)
#define NB     64
#define CC     256
#define EMB    16
#define HW     3136                 // 56*56
#define IDX    16                   // ceil(256^(0.5))
#define SCALEF (256.0f / 240.0f)    // c / (c - INDEX)

#define TOTAL4 ((unsigned)NB * CC * HW / 4)   // 12,845,056 float4
#define SLAB4  (HW / 4)                        // 784 float4 per (n,c) slab

// Per-(n,c) multiplier: SCALEF if channel kept, 0 if dropped.
__device__ float g_mult[NB * CC];

// ---------------------------------------------------------------------------
// Kernel 1: one block per sample row n. Compute activ[n][c] = embeds[n]·table[:,c],
// find the value at sorted index IDX (17th smallest) via rank counting, and
// emit the per-channel multiplier.
// ---------------------------------------------------------------------------
__global__ void drop_thresh_kernel(const float* __restrict__ embeds,
                                   const float* __restrict__ table) {
    __shared__ float s_emb[EMB];
    __shared__ float s_act[CC];
    __shared__ float s_thr;

    const int n = blockIdx.x;
    const int c = threadIdx.x;

    if (c < EMB) s_emb[c] = embeds[n * EMB + c];
    __syncthreads();

    float a = 0.0f;
#pragma unroll
    for (int e = 0; e < EMB; e++)
        a = fmaf(s_emb[e], table[e * CC + c], a);   // coalesced across c
    s_act[c] = a;
    __syncthreads();

    // Rank of this thread's value among the 256 row values.
    int less = 0, leq = 0;
#pragma unroll 8
    for (int j = 0; j < CC; j++) {
        const float v = s_act[j];
        less += (v <  a);
        leq  += (v <= a);
    }
    // Sorted-index-IDX element: #{< v} <= IDX and #{<= v} > IDX.
    // (Unique for the value itself even under ties; multiple tied threads
    //  write the same value.)
    if (less <= IDX && leq > IDX) s_thr = a;
    __syncthreads();

    g_mult[n * CC + c] = (s_thr <= a) ? SCALEF : 0.0f;
}

// ---------------------------------------------------------------------------
// Kernel 2: memory-bound stream. out = x * mult[slab], float4-wide,
// skipping the READ for dropped channels (mult==0 -> pure zero store).
// Touch-once data: cache-streaming loads/stores.
// ---------------------------------------------------------------------------
__global__ void __launch_bounds__(256)
drop_apply_kernel(const float4* __restrict__ x, float4* __restrict__ out) {
    const unsigned stride = gridDim.x * blockDim.x;
    unsigned i = blockIdx.x * blockDim.x + threadIdx.x;
#pragma unroll 4
    for (; i < TOTAL4; i += stride) {
        const unsigned slab = i / SLAB4;      // constant divide -> mulhi
        const float m = g_mult[slab];         // 16 KB table, L1-resident
        float4 v;
        if (m != 0.0f) {
            v = __ldcs(&x[i]);
            v.x *= m; v.y *= m; v.z *= m; v.w *= m;
        } else {
            v = make_float4(0.0f, 0.0f, 0.0f, 0.0f);
        }
        __stcs(&out[i], v);
    }
}

extern "C" void kernel_launch(void* const* d_in, const int* in_sizes, int n_in,
                              void* d_out, int out_size) {
    const float* x      = (const float*)d_in[0];   // [64,256,56,56]
    const float* embeds = (const float*)d_in[1];   // [64,16]
    const float* table  = (const float*)d_in[2];   // [16,256]
    float* out = (float*)d_out;

    drop_thresh_kernel<<<NB, CC>>>(embeds, table);

    // 6272 blocks * 256 threads * 8 grid-stride iters == TOTAL4 exactly.
    const int threads = 256;
    const int blocks  = (int)(TOTAL4 / (threads * 8));
    drop_apply_kernel<<<blocks, threads>>>((const float4*)x, (float4*)out);
}